// round 12
// baseline (speedup 1.0000x reference)
#include <cuda_runtime.h>
#include <cstdint>

#define INV_SQRT2 0.7071067811865476f

// x: (B=64, S=4096, F=256) fp32 contiguous -> out (B, 2048, 512):
//   out[b,s2,2f]   = (x[b,2s2,f] + x[b,2s2+1,f]) * INV_SQRT2
//   out[b,s2,2f+1] = (x[b,2s2,f] - x[b,2s2+1,f]) * INV_SQRT2
//
// FINAL (R7 design — measured best: kernel 74.9us, DRAM 81.6%, 6466 GB/s):
// One-shot kernel, store-contiguous mapping, adjacent unroll x2 with
// compiler-scheduled loads (regs=24 -> occ 82%). Thread (p, j), j in [0,32):
// handles output float4 chunks {j, j+64} and {j+32, j+96} of pair p. Each
// warp's footprint is one dense 2KB-in / 2KB-out window (DRAM row-buffer
// locality). Loads: 8x lane-contiguous LDG.64.CS. Stores: 4x STG.128.CS,
// each a contiguous 512B span across the warp.
//
// Session map (why this shape): persistence -5% (R3,R6); wider vectors
// neutral (R5); forced load batching / 512-thread CTAs -1.6% (R8). The op
// is pinned at the 1:1 R/W HBM ceiling; nothing SM-side binds
// (issue ~10%, LTS ~40% of cap).

__device__ __forceinline__ void haar_chunk(const float2* __restrict__ x0,
                                           const float2* __restrict__ x1,
                                           float4* __restrict__ orow,
                                           int j)
{
    float2 a0 = __ldcs(x0 + j);          // f = 2j, 2j+1
    float2 b0 = __ldcs(x1 + j);
    float2 a1 = __ldcs(x0 + j + 64);     // f = 2j+128, 2j+129
    float2 b1 = __ldcs(x1 + j + 64);

    float4 o0, o1;
    o0.x = (a0.x + b0.x) * INV_SQRT2;
    o0.y = (a0.x - b0.x) * INV_SQRT2;
    o0.z = (a0.y + b0.y) * INV_SQRT2;
    o0.w = (a0.y - b0.y) * INV_SQRT2;
    o1.x = (a1.x + b1.x) * INV_SQRT2;
    o1.y = (a1.x - b1.x) * INV_SQRT2;
    o1.z = (a1.y + b1.y) * INV_SQRT2;
    o1.w = (a1.y - b1.y) * INV_SQRT2;

    __stcs(orow + j,      o0);   // output chunk j      (contiguous over warp)
    __stcs(orow + j + 64, o1);   // output chunk j+64
}

__global__ void __launch_bounds__(256) haar_kernel(const float2* __restrict__ x,
                                                   float4* __restrict__ out,
                                                   int total_threads)
{
    int tid = blockIdx.x * blockDim.x + threadIdx.x;
    if (tid >= total_threads) return;

    int p = tid >> 5;        // pair index (b*S/2 + s2)
    int j = tid & 31;        // base chunk within pair

    const float2* x0 = x + (size_t)p * 256;        // row 2s2   (as float2)
    const float2* x1 = x0 + 128;                   // row 2s2+1
    float4* orow = out + (size_t)p * 128;          // output row (as float4)

    // Two adjacent work items: chunks {j, j+64} and {j+32, j+96}.
    haar_chunk(x0, x1, orow, j);
    haar_chunk(x0, x1, orow, j + 32);
}

extern "C" void kernel_launch(void* const* d_in, const int* in_sizes, int n_in,
                              void* d_out, int out_size)
{
    const float2* x = (const float2*)d_in[0];
    float4* out = (float4*)d_out;

    // 16 input floats per thread -> threads = n / 16.
    int total_threads = in_sizes[0] / 16;

    int threads = 256;
    int blocks = (total_threads + threads - 1) / threads;
    haar_kernel<<<blocks, threads>>>(x, out, total_threads);
}